// round 6
// baseline (speedup 1.0000x reference)
#include <cuda_runtime.h>

#define THREADS      256
#define ATT_BLOCKS   8192
#define BAND_BLOCKS  64
#define REC_BLOCKS   64
#define IDENT_BLOCKS 256
#define GRID_TOTAL   (ATT_BLOCKS + BAND_BLOCKS + REC_BLOCKS + IDENT_BLOCKS)  // 8576
#define BAND_BASE    ATT_BLOCKS
#define REC_BASE     (BAND_BASE + BAND_BLOCKS)
#define IDENT_BASE   (REC_BASE + REC_BLOCKS)

#define CHUNKS       4
#define CHUNK_BYTES  8192
#define CHUNK_F4     512                       // 8KB / 16
#define BLOCK_BYTES  (CHUNKS * CHUNK_BYTES)    // 32KB per att block
// ATT_BLOCKS * BLOCK_BYTES = 8192 * 32768 = 256 MB = whole corr tensor

__device__ float g_att_partial[ATT_BLOCKS];
__device__ float g_band[BAND_BLOCKS];
__device__ float g_rec_sum[REC_BLOCKS];
__device__ float g_rec_cnt[REC_BLOCKS];
__device__ float g_rec_mn[3 * REC_BLOCKS];
__device__ float g_rec_mx[3 * REC_BLOCKS];
__device__ float g_ident[IDENT_BLOCKS];
__device__ unsigned g_count = 0;

typedef unsigned long long ull;
__device__ __forceinline__ ull pk2(float lo, float hi) {
    ull r; asm("mov.b64 %0, {%1, %2};" : "=l"(r) : "f"(lo), "f"(hi)); return r;
}
__device__ __forceinline__ void upk2(float& lo, float& hi, ull v) {
    asm("mov.b64 {%0, %1}, %2;" : "=f"(lo), "=f"(hi) : "l"(v));
}
__device__ __forceinline__ ull fma2_(ull a, ull b, ull c) {
    ull r; asm("fma.rn.f32x2 %0, %1, %2, %3;" : "=l"(r) : "l"(a), "l"(b), "l"(c)); return r;
}
__device__ __forceinline__ ull add2_(ull a, ull b) {
    ull r; asm("add.rn.f32x2 %0, %1, %2;" : "=l"(r) : "l"(a), "l"(b)); return r;
}
__device__ __forceinline__ unsigned smem_u32(const void* p) {
    unsigned a;
    asm("{ .reg .u64 t; cvta.to.shared.u64 t, %1; cvt.u32.u64 %0, t; }" : "=r"(a) : "l"(p));
    return a;
}
__device__ __forceinline__ void mbar_wait0(unsigned mb) {
    asm volatile(
        "{\n\t.reg .pred P;\n\t"
        "W_%=:\n\t"
        "mbarrier.try_wait.parity.acquire.cta.shared::cta.b64 P, [%0], 0, 0x989680;\n\t"
        "@P bra.uni D_%=;\n\t"
        "bra.uni W_%=;\n\t"
        "D_%=:\n\t}"
        :: "r"(mb) : "memory");
}

// Deg-4 Chebyshev of log1p(u)=log((3+z)/2), z=2u-1, u=exp(-|x|); |err|<=~1e-4 abs.
#define SP_C4 (-3.46617e-3f)
#define SP_C3 ( 1.346836e-2f)
#define SP_C2 (-5.540845e-2f)
#define SP_C1 ( 3.3304459e-1f)
#define SP_C0 ( 4.0548119e-1f)

__device__ __forceinline__ float softplus_f(float x) {
    float u = exp2f(fabsf(x) * -1.44269504f);
    float z = fmaf(u, 2.0f, -1.0f);
    float p = fmaf(SP_C4, z, SP_C3);
    p = fmaf(p, z, SP_C2);
    p = fmaf(p, z, SP_C1);
    p = fmaf(p, z, SP_C0);
    return fmaxf(x, 0.0f) + p;
}

#define BRED(var, OP, dst)                                            \
    red[t] = var; __syncthreads();                                    \
    for (int s = THREADS / 2; s > 0; s >>= 1) {                       \
        if (t < s) red[t] = OP(red[t], red[t + s]);                   \
        __syncthreads();                                              \
    }                                                                 \
    if (t == 0) dst = red[0];                                         \
    __syncthreads();
#define ADDOP(a, b) ((a) + (b))

// ---------------------------------------------------------------------------
// att stream via TMA: 4 single-use stages of 8KB bulk-copied into smem.
// Registers stay ~30 (occupancy limited by smem only); TMA engine holds the
// outstanding bytes. Compute: branch-free packed softplus sum from LDS.128.
// ---------------------------------------------------------------------------
__device__ void att_part(int ab, const float4* __restrict__ corr,
                         float4 (*buf)[CHUNK_F4], ull* mbar, float* red) {
    unsigned mb0 = smem_u32(mbar);
    if (threadIdx.x == 0) {
#pragma unroll
        for (int c = 0; c < CHUNKS; ++c)
            asm volatile("mbarrier.init.shared.b64 [%0], 1;" :: "r"(mb0 + c * 8) : "memory");
        asm volatile("fence.proxy.async.shared::cta;" ::: "memory");
    }
    __syncthreads();

    if (threadIdx.x == 0) {
        const char* src = (const char*)corr + (size_t)ab * BLOCK_BYTES;
        unsigned dst0 = smem_u32(buf);
#pragma unroll
        for (int c = 0; c < CHUNKS; ++c) {
            asm volatile("mbarrier.arrive.expect_tx.shared.b64 _, [%0], %1;"
                         :: "r"(mb0 + c * 8), "r"((unsigned)CHUNK_BYTES) : "memory");
            asm volatile("cp.async.bulk.shared::cta.global.mbarrier::complete_tx::bytes "
                         "[%0], [%1], %2, [%3];"
                         :: "r"(dst0 + c * CHUNK_BYTES), "l"(src + (size_t)c * CHUNK_BYTES),
                            "r"((unsigned)CHUNK_BYTES), "r"(mb0 + c * 8) : "memory");
        }
    }

    const ull C4 = pk2(SP_C4, SP_C4);
    const ull C3 = pk2(SP_C3, SP_C3);
    const ull C2 = pk2(SP_C2, SP_C2);
    const ull C1 = pk2(SP_C1, SP_C1);
    const ull C0 = pk2(SP_C0, SP_C0);
    const ull TWO  = pk2(2.0f, 2.0f);
    const ull NEG1 = pk2(-1.0f, -1.0f);

    ull acc2 = pk2(0.f, 0.f);
    float accm = 0.f;
#pragma unroll
    for (int c = 0; c < CHUNKS; ++c) {
        mbar_wait0(mb0 + c * 8);
#pragma unroll
        for (int h = 0; h < 2; ++h) {
            float4 x = buf[c][threadIdx.x + h * THREADS];
            float u0 = exp2f(fabsf(x.x) * -1.44269504f);
            float u1 = exp2f(fabsf(x.y) * -1.44269504f);
            float u2 = exp2f(fabsf(x.z) * -1.44269504f);
            float u3 = exp2f(fabsf(x.w) * -1.44269504f);
            ull uA = pk2(u0, u1), uB = pk2(u2, u3);
            ull zA = fma2_(uA, TWO, NEG1);
            ull zB = fma2_(uB, TWO, NEG1);
            ull pA = fma2_(C4, zA, C3);
            ull pB = fma2_(C4, zB, C3);
            pA = fma2_(pA, zA, C2);  pB = fma2_(pB, zB, C2);
            pA = fma2_(pA, zA, C1);  pB = fma2_(pB, zB, C1);
            pA = fma2_(pA, zA, C0);  pB = fma2_(pB, zB, C0);
            acc2 = add2_(acc2, pA);
            acc2 = add2_(acc2, pB);
            accm += fmaxf(x.x, 0.f) + fmaxf(x.y, 0.f);
            accm += fmaxf(x.z, 0.f) + fmaxf(x.w, 0.f);
        }
    }
    float alo, ahi; upk2(alo, ahi, acc2);
    float acc = accm + alo + ahi;

    // warp-shuffle reduction, then 8 warp sums
#pragma unroll
    for (int o = 16; o > 0; o >>= 1)
        acc += __shfl_xor_sync(0xFFFFFFFFu, acc, o);
    int wid = threadIdx.x >> 5;
    if ((threadIdx.x & 31) == 0) red[wid] = acc;
    __syncthreads();
    if (threadIdx.x == 0) {
        float s = ((red[0] + red[1]) + (red[2] + red[3]))
                + ((red[4] + red[5]) + (red[6] + red[7]));
        g_att_partial[ab] = s;
    }
}

// ---------------------------------------------------------------------------
// band correction: for |i-j|<=2, add  w*bce - softplus = 2*gt*sp - gt*x*(1+2gt)
// gt = band(|i-j|)*(vis_i|vis_j). One block per (vv,b) matrix m in [0,64).
// ---------------------------------------------------------------------------
__device__ void band_part(int m, const float* __restrict__ corr,
                          const int* __restrict__ vis, float* red) {
    const float* cf = corr + ((size_t)m << 20);      // m-th 1024x1024 matrix
    const int* vb = vis + (m & 3) * 16384;           // visibility[b, 0, :]
    float delta = 0.f;
    for (int i = threadIdx.x; i < 1024; i += THREADS) {
        float vi = (vb[i] > 0) ? 1.f : 0.f;
        const float* row = cf + (size_t)i * 1024;
#pragma unroll
        for (int dj = -2; dj <= 2; ++dj) {
            int j = i + dj;
            if ((unsigned)j < 1024u) {
                int d = dj < 0 ? -dj : dj;
                float band = (d == 0) ? 1.f : (d == 1) ? 0.7f : 0.49f;
                float pair = (vi > 0.f || vb[j] > 0) ? 1.f : 0.f;
                float gt = band * pair;
                float x = row[j];
                float sp = softplus_f(x);
                delta += 2.f * gt * sp - gt * x * fmaf(2.f, gt, 1.f);
            }
        }
    }
    int t = threadIdx.x;
    BRED(delta, ADDOP, g_band[m]);
}

// ---------------------------------------------------------------------------
// rec part
// ---------------------------------------------------------------------------
__device__ void rec_part(int rb, const float* __restrict__ rp,
                         const float* __restrict__ gp,
                         const int* __restrict__ vis, float* red) {
    int tid = rb * THREADS + threadIdx.x;
    float sum = 0.f, cnt = 0.f;
    float mn0 = 1e30f, mn1 = 1e30f, mn2 = 1e30f;
    float mx0 = -1e30f, mx1 = -1e30f, mx2 = -1e30f;
    for (int p = tid; p < 65536; p += REC_BLOCKS * THREADS) {
        if (vis[p] > 0) {
            float g0 = gp[3 * p], g1 = gp[3 * p + 1], g2 = gp[3 * p + 2];
            float d0 = rp[3 * p] - g0, d1 = rp[3 * p + 1] - g1, d2 = rp[3 * p + 2] - g2;
            sum += d0 * d0 + d1 * d1 + d2 * d2;
            cnt += 1.f;
            mn0 = fminf(mn0, g0); mn1 = fminf(mn1, g1); mn2 = fminf(mn2, g2);
            mx0 = fmaxf(mx0, g0); mx1 = fmaxf(mx1, g1); mx2 = fmaxf(mx2, g2);
        }
    }
    int t = threadIdx.x;
    BRED(sum, ADDOP, g_rec_sum[rb]);
    BRED(cnt, ADDOP, g_rec_cnt[rb]);
    BRED(mn0, fminf, g_rec_mn[0 * REC_BLOCKS + rb]);
    BRED(mn1, fminf, g_rec_mn[1 * REC_BLOCKS + rb]);
    BRED(mn2, fminf, g_rec_mn[2 * REC_BLOCKS + rb]);
    BRED(mx0, fmaxf, g_rec_mx[0 * REC_BLOCKS + rb]);
    BRED(mx1, fmaxf, g_rec_mx[1 * REC_BLOCKS + rb]);
    BRED(mx2, fmaxf, g_rec_mx[2 * REC_BLOCKS + rb]);
}

// ---------------------------------------------------------------------------
// ident part
// ---------------------------------------------------------------------------
__device__ void ident_part(int blk, const float* __restrict__ pred,
                           const float* __restrict__ proj,
                           const float* __restrict__ tracks, float* red) {
    int v = blk >> 6;
    int b = (blk >> 4) & 3;
    int f = blk & 15;
    int t = threadIdx.x;

    __shared__ float P[12];
    __shared__ float swh[2];
    __shared__ float sres[4];
    if (t < 12) P[t] = proj[(v * 4 + b) * 12 + t];

    const float* tr = tracks + (size_t)(((v * 4 + b) * 16 + f) * 1024) * 2;
    const float* pp = pred + (size_t)((b * 16 + f) * 1024) * 3;

    float mn0 = 1e30f, mn1 = 1e30f, mx0 = -1e30f, mx1 = -1e30f;
    for (int n = t; n < 1024; n += THREADS) {
        float a0 = tr[2 * n], a1 = tr[2 * n + 1];
        if (fabsf(a0) + fabsf(a1) > 1e-6f) {
            mn0 = fminf(mn0, a0); mn1 = fminf(mn1, a1);
            mx0 = fmaxf(mx0, a0); mx1 = fmaxf(mx1, a1);
        }
    }
    BRED(mn0, fminf, sres[0]);
    BRED(mn1, fminf, sres[1]);
    BRED(mx0, fmaxf, sres[2]);
    BRED(mx1, fmaxf, sres[3]);
    if (t == 0) {
        // no valid point: mx-mn = -2e30 -> max(224, ...) = 224, matches reference
        swh[0] = fmaxf(224.0f, sres[2] - sres[0] + 1e-6f);
        swh[1] = fmaxf(224.0f, sres[3] - sres[1] + 1e-6f);
    }
    __syncthreads();
    float wh0 = swh[0], wh1 = swh[1];

    float s = 0.f;
    for (int n = t; n < 1024; n += THREADS) {
        float px = pp[3 * n], py = pp[3 * n + 1], pz = pp[3 * n + 2];
        // Left-to-right FMA contraction, matching XLA's k-loop order.
        float h0 = __fmul_rn(P[0], px);
        h0 = __fmaf_rn(P[1], py, h0);
        h0 = __fmaf_rn(P[2], pz, h0);
        h0 = __fadd_rn(h0, P[3]);
        float h1 = __fmul_rn(P[4], px);
        h1 = __fmaf_rn(P[5], py, h1);
        h1 = __fmaf_rn(P[6], pz, h1);
        h1 = __fadd_rn(h1, P[7]);
        float h2 = __fmul_rn(P[8], px);
        h2 = __fmaf_rn(P[9], py, h2);
        h2 = __fmaf_rn(P[10], pz, h2);
        h2 = __fadd_rn(h2, P[11]);

        float d = __fadd_rn(h2, 1e-10f);
        float p20 = __fdiv_rn(h0, d);
        float p21 = __fdiv_rn(h1, d);
        float a0 = tr[2 * n], a1 = tr[2 * n + 1];
        float e0 = __fdiv_rn(__fadd_rn(p20, -a0), wh0);
        float e1 = __fdiv_rn(__fadd_rn(p21, -a1), wh1);
        s += __fmul_rn(e0, e0) + __fmul_rn(e1, e1);
    }
    BRED(s, ADDOP, g_ident[blk]);
    if (t == 0) g_ident[blk] *= (1.0f / 1024.0f);
}

// ---------------------------------------------------------------------------
// fused kernel; last-arriving block does the deterministic combine.
// ---------------------------------------------------------------------------
__global__ void __launch_bounds__(THREADS)
fused_kernel(const float* __restrict__ rp, const float* __restrict__ gp,
             const int* __restrict__ vis, const float* __restrict__ proj,
             const float* __restrict__ tracks,
             const float4* __restrict__ corr, float* __restrict__ out) {
    __shared__ alignas(128) float4 buf[CHUNKS][CHUNK_F4];    // 32 KB TMA staging
    __shared__ alignas(8) ull mbar[CHUNKS];
    __shared__ float red[THREADS];
    __shared__ int sdone;
    int bid = blockIdx.x;

    if (bid < ATT_BLOCKS) {
        att_part(bid, corr, buf, mbar, red);
    } else if (bid < REC_BASE) {
        band_part(bid - BAND_BASE, (const float*)corr, vis, red);
    } else if (bid < IDENT_BASE) {
        rec_part(bid - REC_BASE, rp, gp, vis, red);
    } else {
        ident_part(bid - IDENT_BASE, rp, proj, tracks, red);
    }

    __syncthreads();
    if (threadIdx.x == 0) {
        __threadfence();
        unsigned old = atomicAdd(&g_count, 1u);
        sdone = (old == GRID_TOTAL - 1) ? 1 : 0;
    }
    __syncthreads();
    if (!sdone) return;

    int tid = threadIdx.x;

    // attention = stream softplus sum + band correction
    float a = 0.f;
    for (int k = tid; k < ATT_BLOCKS; k += THREADS) a += __ldcg(&g_att_partial[k]);
    if (tid < BAND_BLOCKS) a += __ldcg(&g_band[tid]);
    red[tid] = a; __syncthreads();
    for (int s = THREADS / 2; s > 0; s >>= 1) {
        if (tid < s) red[tid] += red[tid + s];
        __syncthreads();
    }
    float att = red[0] * (1.0f / 67108864.0f);
    __syncthreads();

    // identity
    red[tid] = __ldcg(&g_ident[tid]); __syncthreads();
    for (int s = THREADS / 2; s > 0; s >>= 1) {
        if (tid < s) red[tid] += red[tid + s];
        __syncthreads();
    }
    float ident = red[0] * (1.0f / 256.0f);
    __syncthreads();

    // reconstruction
    red[tid] = (tid < REC_BLOCKS) ? __ldcg(&g_rec_sum[tid]) : 0.f; __syncthreads();
    for (int s = THREADS / 2; s > 0; s >>= 1) {
        if (tid < s) red[tid] += red[tid + s];
        __syncthreads();
    }
    float recSum = red[0]; __syncthreads();

    red[tid] = (tid < REC_BLOCKS) ? __ldcg(&g_rec_cnt[tid]) : 0.f; __syncthreads();
    for (int s = THREADS / 2; s > 0; s >>= 1) {
        if (tid < s) red[tid] += red[tid + s];
        __syncthreads();
    }
    float cnt = red[0]; __syncthreads();

    float mn[3], mx[3];
#pragma unroll
    for (int c = 0; c < 3; ++c) {
        red[tid] = (tid < REC_BLOCKS) ? __ldcg(&g_rec_mn[c * REC_BLOCKS + tid]) : 1e30f;
        __syncthreads();
        for (int s = THREADS / 2; s > 0; s >>= 1) {
            if (tid < s) red[tid] = fminf(red[tid], red[tid + s]);
            __syncthreads();
        }
        mn[c] = red[0]; __syncthreads();
        red[tid] = (tid < REC_BLOCKS) ? __ldcg(&g_rec_mx[c * REC_BLOCKS + tid]) : -1e30f;
        __syncthreads();
        for (int s = THREADS / 2; s > 0; s >>= 1) {
            if (tid < s) red[tid] = fmaxf(red[tid], red[tid + s]);
            __syncthreads();
        }
        mx[c] = red[0]; __syncthreads();
    }

    if (tid == 0) {
        float num = cnt * 3.0f;
        float mse = recSum / fmaxf(num, 1.0f);
        float sc = fmaxf(fmaxf(mx[0] - mn[0], mx[1] - mn[1]), mx[2] - mn[2]) + 1e-6f;
        if (!(num > 0.f)) sc = 1.0f;
        float rec = mse / (sc * sc);
        out[0] = rec + ident + 0.5f * att;
        out[1] = rec;
        out[2] = ident;
        out[3] = att;
        g_count = 0;   // reset for next graph replay
    }
}

extern "C" void kernel_launch(void* const* d_in, const int* in_sizes, int n_in,
                              void* d_out, int out_size) {
    const float*  rp     = (const float*)d_in[0];   // refined_points [4,16,1024,3]
    const float*  gp     = (const float*)d_in[1];   // gt_points
    const int*    vis    = (const int*)d_in[2];     // visibility [4,16,1024]
    const float*  proj   = (const float*)d_in[3];   // projection [4,4,3,4]
    const float*  tracks = (const float*)d_in[4];   // tracks_2d [4,4,16,1024,2]
    const float4* corr   = (const float4*)d_in[5];  // corr [4,4,4,1024,1024]

    fused_kernel<<<GRID_TOTAL, THREADS>>>(rp, gp, vis, proj, tracks, corr, (float*)d_out);
}

// round 7
// speedup vs baseline: 1.5510x; 1.5510x over previous
#include <cuda_runtime.h>

#define THREADS      256
#define ATT_BLOCKS   4096
#define BAND_BLOCKS  64
#define REC_BLOCKS   64
#define IDENT_BLOCKS 256
#define GRID_TOTAL   (ATT_BLOCKS + BAND_BLOCKS + REC_BLOCKS + IDENT_BLOCKS)  // 4480
#define BAND_BASE    ATT_BLOCKS
#define REC_BASE     (BAND_BASE + BAND_BLOCKS)
#define IDENT_BASE   (REC_BASE + REC_BLOCKS)

#define STAGE_F4     512                    // 8KB stage
#define NSTAGES      8                      // block handles 4096 float4 = 64KB
#define NBUF         3                      // 24KB smem ring, <=2 stages in flight
#define BLOCK_F4     (STAGE_F4 * NSTAGES)   // 4096
// ATT_BLOCKS * BLOCK_F4 * 16B = 4096 * 64KB = 256 MB = whole corr tensor

__device__ float g_att_partial[ATT_BLOCKS];
__device__ float g_band[BAND_BLOCKS];
__device__ float g_rec_sum[REC_BLOCKS];
__device__ float g_rec_cnt[REC_BLOCKS];
__device__ float g_rec_mn[3 * REC_BLOCKS];
__device__ float g_rec_mx[3 * REC_BLOCKS];
__device__ float g_ident[IDENT_BLOCKS];
__device__ unsigned g_count = 0;

typedef unsigned long long ull;
__device__ __forceinline__ ull pk2(float lo, float hi) {
    ull r; asm("mov.b64 %0, {%1, %2};" : "=l"(r) : "f"(lo), "f"(hi)); return r;
}
__device__ __forceinline__ void upk2(float& lo, float& hi, ull v) {
    asm("mov.b64 {%0, %1}, %2;" : "=f"(lo), "=f"(hi) : "l"(v));
}
__device__ __forceinline__ ull fma2_(ull a, ull b, ull c) {
    ull r; asm("fma.rn.f32x2 %0, %1, %2, %3;" : "=l"(r) : "l"(a), "l"(b), "l"(c)); return r;
}
__device__ __forceinline__ ull add2_(ull a, ull b) {
    ull r; asm("add.rn.f32x2 %0, %1, %2;" : "=l"(r) : "l"(a), "l"(b)); return r;
}
__device__ __forceinline__ unsigned smem_u32(const void* p) {
    unsigned a;
    asm("{ .reg .u64 t; cvta.to.shared.u64 t, %1; cvt.u32.u64 %0, t; }" : "=r"(a) : "l"(p));
    return a;
}
__device__ __forceinline__ void cp16(unsigned dst, const void* src) {
    asm volatile("cp.async.cg.shared.global [%0], [%1], 16;" :: "r"(dst), "l"(src) : "memory");
}
__device__ __forceinline__ void cp_commit() {
    asm volatile("cp.async.commit_group;" ::: "memory");
}
template <int N>
__device__ __forceinline__ void cp_wait() {
    asm volatile("cp.async.wait_group %0;" :: "n"(N) : "memory");
}

// Deg-4 Chebyshev of log1p(u)=log((3+z)/2), z=2u-1, u=exp(-|x|); |err|<=~1e-4 abs.
#define SP_C4 (-3.46617e-3f)
#define SP_C3 ( 1.346836e-2f)
#define SP_C2 (-5.540845e-2f)
#define SP_C1 ( 3.3304459e-1f)
#define SP_C0 ( 4.0548119e-1f)

__device__ __forceinline__ float softplus_f(float x) {
    float u = exp2f(fabsf(x) * -1.44269504f);
    float z = fmaf(u, 2.0f, -1.0f);
    float p = fmaf(SP_C4, z, SP_C3);
    p = fmaf(p, z, SP_C2);
    p = fmaf(p, z, SP_C1);
    p = fmaf(p, z, SP_C0);
    return fmaxf(x, 0.0f) + p;
}

#define BRED(var, OP, dst)                                            \
    red[t] = var; __syncthreads();                                    \
    for (int s = THREADS / 2; s > 0; s >>= 1) {                       \
        if (t < s) red[t] = OP(red[t], red[t + s]);                   \
        __syncthreads();                                              \
    }                                                                 \
    if (t == 0) dst = red[0];                                         \
    __syncthreads();
#define ADDOP(a, b) ((a) + (b))

// ---------------------------------------------------------------------------
// att stream via per-thread cp.async: 8KB stages, 3-buffer ring, <=2 stages
// outstanding -> ~16KB in flight per CTA (~96KB/SM). Branch-free packed
// softplus sum; band correction handled by separate blocks.
// ---------------------------------------------------------------------------
__device__ void att_part(int ab, const float4* __restrict__ corr,
                         float4 (*abuf)[STAGE_F4], float* red) {
    const float4* src = corr + (size_t)ab * BLOCK_F4;
    unsigned sbase = smem_u32(abuf);
    int tid = threadIdx.x;

    // issue stage s into ring buffer (s % NBUF): 2 x 16B per thread
#define ISSUE(s) do {                                                          \
        unsigned d = sbase + ((s) % NBUF) * (STAGE_F4 * 16);                   \
        const float4* g = src + (s) * STAGE_F4;                                \
        cp16(d + tid * 16,                 (const void*)(g + tid));            \
        cp16(d + (tid + THREADS) * 16,     (const void*)(g + tid + THREADS));  \
        cp_commit();                                                           \
    } while (0)

    ISSUE(0); ISSUE(1); ISSUE(2);

    const ull C4 = pk2(SP_C4, SP_C4);
    const ull C3 = pk2(SP_C3, SP_C3);
    const ull C2 = pk2(SP_C2, SP_C2);
    const ull C1 = pk2(SP_C1, SP_C1);
    const ull C0 = pk2(SP_C0, SP_C0);
    const ull TWO  = pk2(2.0f, 2.0f);
    const ull NEG1 = pk2(-1.0f, -1.0f);

    ull acc2 = pk2(0.f, 0.f);
    float accm = 0.f;

#pragma unroll
    for (int s = 0; s < NSTAGES; ++s) {
        // ensure group s complete (keep up to 2 younger groups in flight)
        if (s < NSTAGES - 2)      cp_wait<2>();
        else if (s == NSTAGES - 2) cp_wait<1>();
        else                       cp_wait<0>();
        __syncthreads();
        const float4* bs = abuf[s % NBUF];
#pragma unroll
        for (int h = 0; h < 2; ++h) {
            float4 x = bs[tid + h * THREADS];
            float u0 = exp2f(fabsf(x.x) * -1.44269504f);
            float u1 = exp2f(fabsf(x.y) * -1.44269504f);
            float u2 = exp2f(fabsf(x.z) * -1.44269504f);
            float u3 = exp2f(fabsf(x.w) * -1.44269504f);
            ull uA = pk2(u0, u1), uB = pk2(u2, u3);
            ull zA = fma2_(uA, TWO, NEG1);
            ull zB = fma2_(uB, TWO, NEG1);
            ull pA = fma2_(C4, zA, C3);
            ull pB = fma2_(C4, zB, C3);
            pA = fma2_(pA, zA, C2);  pB = fma2_(pB, zB, C2);
            pA = fma2_(pA, zA, C1);  pB = fma2_(pB, zB, C1);
            pA = fma2_(pA, zA, C0);  pB = fma2_(pB, zB, C0);
            acc2 = add2_(acc2, pA);
            acc2 = add2_(acc2, pB);
            accm += fmaxf(x.x, 0.f) + fmaxf(x.y, 0.f);
            accm += fmaxf(x.z, 0.f) + fmaxf(x.w, 0.f);
        }
        __syncthreads();               // all threads done reading buf[s%NBUF]
        if (s + NBUF < NSTAGES) ISSUE(s + NBUF);
    }
#undef ISSUE

    float alo, ahi; upk2(alo, ahi, acc2);
    float acc = accm + alo + ahi;

#pragma unroll
    for (int o = 16; o > 0; o >>= 1)
        acc += __shfl_xor_sync(0xFFFFFFFFu, acc, o);
    int wid = tid >> 5;
    if ((tid & 31) == 0) red[wid] = acc;
    __syncthreads();
    if (tid == 0) {
        float s = ((red[0] + red[1]) + (red[2] + red[3]))
                + ((red[4] + red[5]) + (red[6] + red[7]));
        g_att_partial[ab] = s;
    }
}

// ---------------------------------------------------------------------------
// band correction: for |i-j|<=2, add  w*bce - softplus = 2*gt*sp - gt*x*(1+2gt)
// gt = band(|i-j|)*(vis_i|vis_j). One block per (vv,b) matrix m in [0,64).
// softplus here is bit-identical to the stream path (same rn ops), so the
// correction cancels the stream's plain softplus exactly.
// ---------------------------------------------------------------------------
__device__ void band_part(int m, const float* __restrict__ corr,
                          const int* __restrict__ vis, float* red) {
    const float* cf = corr + ((size_t)m << 20);      // m-th 1024x1024 matrix
    const int* vb = vis + (m & 3) * 16384;           // visibility[b, 0, :]
    float delta = 0.f;
    for (int i = threadIdx.x; i < 1024; i += THREADS) {
        float vi = (vb[i] > 0) ? 1.f : 0.f;
        const float* row = cf + (size_t)i * 1024;
#pragma unroll
        for (int dj = -2; dj <= 2; ++dj) {
            int j = i + dj;
            if ((unsigned)j < 1024u) {
                int d = dj < 0 ? -dj : dj;
                float band = (d == 0) ? 1.f : (d == 1) ? 0.7f : 0.49f;
                float pair = (vi > 0.f || vb[j] > 0) ? 1.f : 0.f;
                float gt = band * pair;
                float x = row[j];
                float sp = softplus_f(x);
                delta += 2.f * gt * sp - gt * x * fmaf(2.f, gt, 1.f);
            }
        }
    }
    int t = threadIdx.x;
    BRED(delta, ADDOP, g_band[m]);
}

// ---------------------------------------------------------------------------
// rec part
// ---------------------------------------------------------------------------
__device__ void rec_part(int rb, const float* __restrict__ rp,
                         const float* __restrict__ gp,
                         const int* __restrict__ vis, float* red) {
    int tid = rb * THREADS + threadIdx.x;
    float sum = 0.f, cnt = 0.f;
    float mn0 = 1e30f, mn1 = 1e30f, mn2 = 1e30f;
    float mx0 = -1e30f, mx1 = -1e30f, mx2 = -1e30f;
    for (int p = tid; p < 65536; p += REC_BLOCKS * THREADS) {
        if (vis[p] > 0) {
            float g0 = gp[3 * p], g1 = gp[3 * p + 1], g2 = gp[3 * p + 2];
            float d0 = rp[3 * p] - g0, d1 = rp[3 * p + 1] - g1, d2 = rp[3 * p + 2] - g2;
            sum += d0 * d0 + d1 * d1 + d2 * d2;
            cnt += 1.f;
            mn0 = fminf(mn0, g0); mn1 = fminf(mn1, g1); mn2 = fminf(mn2, g2);
            mx0 = fmaxf(mx0, g0); mx1 = fmaxf(mx1, g1); mx2 = fmaxf(mx2, g2);
        }
    }
    int t = threadIdx.x;
    BRED(sum, ADDOP, g_rec_sum[rb]);
    BRED(cnt, ADDOP, g_rec_cnt[rb]);
    BRED(mn0, fminf, g_rec_mn[0 * REC_BLOCKS + rb]);
    BRED(mn1, fminf, g_rec_mn[1 * REC_BLOCKS + rb]);
    BRED(mn2, fminf, g_rec_mn[2 * REC_BLOCKS + rb]);
    BRED(mx0, fmaxf, g_rec_mx[0 * REC_BLOCKS + rb]);
    BRED(mx1, fmaxf, g_rec_mx[1 * REC_BLOCKS + rb]);
    BRED(mx2, fmaxf, g_rec_mx[2 * REC_BLOCKS + rb]);
}

// ---------------------------------------------------------------------------
// ident part
// ---------------------------------------------------------------------------
__device__ void ident_part(int blk, const float* __restrict__ pred,
                           const float* __restrict__ proj,
                           const float* __restrict__ tracks, float* red) {
    int v = blk >> 6;
    int b = (blk >> 4) & 3;
    int f = blk & 15;
    int t = threadIdx.x;

    __shared__ float P[12];
    __shared__ float swh[2];
    __shared__ float sres[4];
    if (t < 12) P[t] = proj[(v * 4 + b) * 12 + t];

    const float* tr = tracks + (size_t)(((v * 4 + b) * 16 + f) * 1024) * 2;
    const float* pp = pred + (size_t)((b * 16 + f) * 1024) * 3;

    float mn0 = 1e30f, mn1 = 1e30f, mx0 = -1e30f, mx1 = -1e30f;
    for (int n = t; n < 1024; n += THREADS) {
        float a0 = tr[2 * n], a1 = tr[2 * n + 1];
        if (fabsf(a0) + fabsf(a1) > 1e-6f) {
            mn0 = fminf(mn0, a0); mn1 = fminf(mn1, a1);
            mx0 = fmaxf(mx0, a0); mx1 = fmaxf(mx1, a1);
        }
    }
    BRED(mn0, fminf, sres[0]);
    BRED(mn1, fminf, sres[1]);
    BRED(mx0, fmaxf, sres[2]);
    BRED(mx1, fmaxf, sres[3]);
    if (t == 0) {
        // no valid point: mx-mn = -2e30 -> max(224, ...) = 224, matches reference
        swh[0] = fmaxf(224.0f, sres[2] - sres[0] + 1e-6f);
        swh[1] = fmaxf(224.0f, sres[3] - sres[1] + 1e-6f);
    }
    __syncthreads();
    float wh0 = swh[0], wh1 = swh[1];

    float s = 0.f;
    for (int n = t; n < 1024; n += THREADS) {
        float px = pp[3 * n], py = pp[3 * n + 1], pz = pp[3 * n + 2];
        // Left-to-right FMA contraction, matching XLA's k-loop order.
        float h0 = __fmul_rn(P[0], px);
        h0 = __fmaf_rn(P[1], py, h0);
        h0 = __fmaf_rn(P[2], pz, h0);
        h0 = __fadd_rn(h0, P[3]);
        float h1 = __fmul_rn(P[4], px);
        h1 = __fmaf_rn(P[5], py, h1);
        h1 = __fmaf_rn(P[6], pz, h1);
        h1 = __fadd_rn(h1, P[7]);
        float h2 = __fmul_rn(P[8], px);
        h2 = __fmaf_rn(P[9], py, h2);
        h2 = __fmaf_rn(P[10], pz, h2);
        h2 = __fadd_rn(h2, P[11]);

        float d = __fadd_rn(h2, 1e-10f);
        float p20 = __fdiv_rn(h0, d);
        float p21 = __fdiv_rn(h1, d);
        float a0 = tr[2 * n], a1 = tr[2 * n + 1];
        float e0 = __fdiv_rn(__fadd_rn(p20, -a0), wh0);
        float e1 = __fdiv_rn(__fadd_rn(p21, -a1), wh1);
        s += __fmul_rn(e0, e0) + __fmul_rn(e1, e1);
    }
    BRED(s, ADDOP, g_ident[blk]);
    if (t == 0) g_ident[blk] *= (1.0f / 1024.0f);
}

// ---------------------------------------------------------------------------
// fused kernel; last-arriving block does the deterministic combine.
// ---------------------------------------------------------------------------
__global__ void __launch_bounds__(THREADS)
fused_kernel(const float* __restrict__ rp, const float* __restrict__ gp,
             const int* __restrict__ vis, const float* __restrict__ proj,
             const float* __restrict__ tracks,
             const float4* __restrict__ corr, float* __restrict__ out) {
    __shared__ alignas(16) float4 abuf[NBUF][STAGE_F4];   // 24KB cp.async ring
    __shared__ float red[THREADS];
    __shared__ int sdone;
    int bid = blockIdx.x;

    if (bid < ATT_BLOCKS) {
        att_part(bid, corr, abuf, red);
    } else if (bid < REC_BASE) {
        band_part(bid - BAND_BASE, (const float*)corr, vis, red);
    } else if (bid < IDENT_BASE) {
        rec_part(bid - REC_BASE, rp, gp, vis, red);
    } else {
        ident_part(bid - IDENT_BASE, rp, proj, tracks, red);
    }

    __syncthreads();
    if (threadIdx.x == 0) {
        __threadfence();
        unsigned old = atomicAdd(&g_count, 1u);
        sdone = (old == GRID_TOTAL - 1) ? 1 : 0;
    }
    __syncthreads();
    if (!sdone) return;

    int tid = threadIdx.x;

    // attention = stream softplus sum + band correction
    float a = 0.f;
    for (int k = tid; k < ATT_BLOCKS; k += THREADS) a += __ldcg(&g_att_partial[k]);
    if (tid < BAND_BLOCKS) a += __ldcg(&g_band[tid]);
    red[tid] = a; __syncthreads();
    for (int s = THREADS / 2; s > 0; s >>= 1) {
        if (tid < s) red[tid] += red[tid + s];
        __syncthreads();
    }
    float att = red[0] * (1.0f / 67108864.0f);
    __syncthreads();

    // identity
    red[tid] = __ldcg(&g_ident[tid]); __syncthreads();
    for (int s = THREADS / 2; s > 0; s >>= 1) {
        if (tid < s) red[tid] += red[tid + s];
        __syncthreads();
    }
    float ident = red[0] * (1.0f / 256.0f);
    __syncthreads();

    // reconstruction
    red[tid] = (tid < REC_BLOCKS) ? __ldcg(&g_rec_sum[tid]) : 0.f; __syncthreads();
    for (int s = THREADS / 2; s > 0; s >>= 1) {
        if (tid < s) red[tid] += red[tid + s];
        __syncthreads();
    }
    float recSum = red[0]; __syncthreads();

    red[tid] = (tid < REC_BLOCKS) ? __ldcg(&g_rec_cnt[tid]) : 0.f; __syncthreads();
    for (int s = THREADS / 2; s > 0; s >>= 1) {
        if (tid < s) red[tid] += red[tid + s];
        __syncthreads();
    }
    float cnt = red[0]; __syncthreads();

    float mn[3], mx[3];
#pragma unroll
    for (int c = 0; c < 3; ++c) {
        red[tid] = (tid < REC_BLOCKS) ? __ldcg(&g_rec_mn[c * REC_BLOCKS + tid]) : 1e30f;
        __syncthreads();
        for (int s = THREADS / 2; s > 0; s >>= 1) {
            if (tid < s) red[tid] = fminf(red[tid], red[tid + s]);
            __syncthreads();
        }
        mn[c] = red[0]; __syncthreads();
        red[tid] = (tid < REC_BLOCKS) ? __ldcg(&g_rec_mx[c * REC_BLOCKS + tid]) : -1e30f;
        __syncthreads();
        for (int s = THREADS / 2; s > 0; s >>= 1) {
            if (tid < s) red[tid] = fmaxf(red[tid], red[tid + s]);
            __syncthreads();
        }
        mx[c] = red[0]; __syncthreads();
    }

    if (tid == 0) {
        float num = cnt * 3.0f;
        float mse = recSum / fmaxf(num, 1.0f);
        float sc = fmaxf(fmaxf(mx[0] - mn[0], mx[1] - mn[1]), mx[2] - mn[2]) + 1e-6f;
        if (!(num > 0.f)) sc = 1.0f;
        float rec = mse / (sc * sc);
        out[0] = rec + ident + 0.5f * att;
        out[1] = rec;
        out[2] = ident;
        out[3] = att;
        g_count = 0;   // reset for next graph replay
    }
}

extern "C" void kernel_launch(void* const* d_in, const int* in_sizes, int n_in,
                              void* d_out, int out_size) {
    const float*  rp     = (const float*)d_in[0];   // refined_points [4,16,1024,3]
    const float*  gp     = (const float*)d_in[1];   // gt_points
    const int*    vis    = (const int*)d_in[2];     // visibility [4,16,1024]
    const float*  proj   = (const float*)d_in[3];   // projection [4,4,3,4]
    const float*  tracks = (const float*)d_in[4];   // tracks_2d [4,4,16,1024,2]
    const float4* corr   = (const float4*)d_in[5];  // corr [4,4,4,1024,1024]

    fused_kernel<<<GRID_TOTAL, THREADS>>>(rp, gp, vis, proj, tracks, corr, (float*)d_out);
}

// round 8
// speedup vs baseline: 1.8055x; 1.1641x over previous
#include <cuda_runtime.h>

#define THREADS      256
#define ATT_BLOCKS   8192
#define BAND_BLOCKS  64
#define REC_BLOCKS   64
#define IDENT_BLOCKS 256
#define GRID_TOTAL   (ATT_BLOCKS + BAND_BLOCKS + REC_BLOCKS + IDENT_BLOCKS)  // 8576
#define BAND_BASE    ATT_BLOCKS
#define REC_BASE     (BAND_BASE + BAND_BLOCKS)
#define IDENT_BASE   (REC_BASE + REC_BLOCKS)
#define ATT_ITERS    8
#define ATT_STRIDE   (ATT_BLOCKS * THREADS)    // 2097152 float4 per iter
// total float4 = V*V*B*N*N/4 = 16777216 = ATT_STRIDE * ATT_ITERS

__device__ float g_att_partial[ATT_BLOCKS];
__device__ float g_band[BAND_BLOCKS];
__device__ float g_rec_sum[REC_BLOCKS];
__device__ float g_rec_cnt[REC_BLOCKS];
__device__ float g_rec_mn[3 * REC_BLOCKS];
__device__ float g_rec_mx[3 * REC_BLOCKS];
__device__ float g_ident[IDENT_BLOCKS];
__device__ unsigned g_count = 0;

typedef unsigned long long ull;
__device__ __forceinline__ ull pk2(float lo, float hi) {
    ull r; asm("mov.b64 %0, {%1, %2};" : "=l"(r) : "f"(lo), "f"(hi)); return r;
}
__device__ __forceinline__ void upk2(float& lo, float& hi, ull v) {
    asm("mov.b64 {%0, %1}, %2;" : "=f"(lo), "=f"(hi) : "l"(v));
}
__device__ __forceinline__ ull fma2_(ull a, ull b, ull c) {
    ull r; asm("fma.rn.f32x2 %0, %1, %2, %3;" : "=l"(r) : "l"(a), "l"(b), "l"(c)); return r;
}

// log1p(u), u = exp(-|x|) in (0,1]: deg-4 poly DIRECT in u (re-expansion of the
// verified z=2u-1 Chebyshev form; |err| <= ~1e-4 abs; p(1)=ln2, p(0.5) err 1.6e-5)
#define SP_D4 (-5.545872e-2f)
#define SP_D3 ( 2.1866432e-1f)
#define SP_D2 (-4.664422e-1f)
#define SP_D1 ( 9.962625e-1f)
#define SP_D0 ( 9.362e-5f)

__device__ __forceinline__ float softplus_f(float x) {
    float u = exp2f(fabsf(x) * -1.44269504f);
    float p = fmaf(SP_D4, u, SP_D3);
    p = fmaf(p, u, SP_D2);
    p = fmaf(p, u, SP_D1);
    p = fmaf(p, u, SP_D0);         // note: band path keeps d0 inline
    return fmaxf(x, 0.0f) + __fmul_rn(p, u) + 0.f;   // max + u*poly
}

#define BRED(var, OP, dst)                                            \
    red[t] = var; __syncthreads();                                    \
    for (int s = THREADS / 2; s > 0; s >>= 1) {                       \
        if (t < s) red[t] = OP(red[t], red[t + s]);                   \
        __syncthreads();                                              \
    }                                                                 \
    if (t == 0) dst = red[0];                                         \
    __syncthreads();
#define ADDOP(a, b) ((a) + (b))

// ---------------------------------------------------------------------------
// att stream: front-batched 8x LDG.128 (R5 skeleton), branch-free, minimal
// instruction count: per float4 = 4x(FMUL+MUFU) + 8 fma2 + 4 FMAX + 2 FADD.
// The poly's constant term d0 is added analytically (32*d0 per thread).
// ---------------------------------------------------------------------------
__device__ void att_part(int ab, const float4* __restrict__ corr, float* red) {
    int tid = threadIdx.x;
    unsigned base = (unsigned)ab * THREADS + tid;

    float4 v[ATT_ITERS];
#pragma unroll
    for (int it = 0; it < ATT_ITERS; ++it)
        v[it] = __ldcs(&corr[base + (unsigned)it * ATT_STRIDE]);

    const ull D4 = pk2(SP_D4, SP_D4);
    const ull D3 = pk2(SP_D3, SP_D3);
    const ull D2 = pk2(SP_D2, SP_D2);
    const ull D1 = pk2(SP_D1, SP_D1);

    ull accA = pk2(0.f, 0.f);
    ull accB = pk2(0.f, 0.f);
    float accm = 0.f;
#pragma unroll
    for (int it = 0; it < ATT_ITERS; ++it) {
        float4 x = v[it];
        float u0 = exp2f(fabsf(x.x) * -1.44269504f);
        float u1 = exp2f(fabsf(x.y) * -1.44269504f);
        float u2 = exp2f(fabsf(x.z) * -1.44269504f);
        float u3 = exp2f(fabsf(x.w) * -1.44269504f);
        ull uA = pk2(u0, u1), uB = pk2(u2, u3);
        ull pA = fma2_(D4, uA, D3);
        ull pB = fma2_(D4, uB, D3);
        pA = fma2_(pA, uA, D2);  pB = fma2_(pB, uB, D2);
        pA = fma2_(pA, uA, D1);  pB = fma2_(pB, uB, D1);
        accA = fma2_(pA, uA, accA);       // += u * poly_no_d0(u)
        accB = fma2_(pB, uB, accB);
        accm += fmaxf(x.x, 0.f) + fmaxf(x.y, 0.f);
        accm += fmaxf(x.z, 0.f) + fmaxf(x.w, 0.f);
    }
    float a0, a1, b0, b1;
    upk2(a0, a1, accA);
    upk2(b0, b1, accB);
    // + 32 elements worth of the missing d0 constant term
    float acc = accm + (a0 + a1) + (b0 + b1) + 32.0f * SP_D0;

#pragma unroll
    for (int o = 16; o > 0; o >>= 1)
        acc += __shfl_xor_sync(0xFFFFFFFFu, acc, o);
    int wid = tid >> 5;
    if ((tid & 31) == 0) red[wid] = acc;
    __syncthreads();
    if (tid == 0) {
        float s = ((red[0] + red[1]) + (red[2] + red[3]))
                + ((red[4] + red[5]) + (red[6] + red[7]));
        g_att_partial[ab] = s;
    }
}

// ---------------------------------------------------------------------------
// band correction: for |i-j|<=2, add  w*bce - softplus = 2*gt*sp - gt*x*(1+2gt)
// gt = band(|i-j|)*(vis_i|vis_j). One block per (vv,b) matrix m in [0,64).
// ---------------------------------------------------------------------------
__device__ void band_part(int m, const float* __restrict__ corr,
                          const int* __restrict__ vis, float* red) {
    const float* cf = corr + ((size_t)m << 20);      // m-th 1024x1024 matrix
    const int* vb = vis + (m & 3) * 16384;           // visibility[b, 0, :]
    float delta = 0.f;
    for (int i = threadIdx.x; i < 1024; i += THREADS) {
        float vi = (vb[i] > 0) ? 1.f : 0.f;
        const float* row = cf + (size_t)i * 1024;
#pragma unroll
        for (int dj = -2; dj <= 2; ++dj) {
            int j = i + dj;
            if ((unsigned)j < 1024u) {
                int d = dj < 0 ? -dj : dj;
                float band = (d == 0) ? 1.f : (d == 1) ? 0.7f : 0.49f;
                float pair = (vi > 0.f || vb[j] > 0) ? 1.f : 0.f;
                float gt = band * pair;
                float x = row[j];
                float sp = softplus_f(x);
                delta += 2.f * gt * sp - gt * x * fmaf(2.f, gt, 1.f);
            }
        }
    }
    int t = threadIdx.x;
    BRED(delta, ADDOP, g_band[m]);
}

// ---------------------------------------------------------------------------
// rec part
// ---------------------------------------------------------------------------
__device__ void rec_part(int rb, const float* __restrict__ rp,
                         const float* __restrict__ gp,
                         const int* __restrict__ vis, float* red) {
    int tid = rb * THREADS + threadIdx.x;
    float sum = 0.f, cnt = 0.f;
    float mn0 = 1e30f, mn1 = 1e30f, mn2 = 1e30f;
    float mx0 = -1e30f, mx1 = -1e30f, mx2 = -1e30f;
    for (int p = tid; p < 65536; p += REC_BLOCKS * THREADS) {
        if (vis[p] > 0) {
            float g0 = gp[3 * p], g1 = gp[3 * p + 1], g2 = gp[3 * p + 2];
            float d0 = rp[3 * p] - g0, d1 = rp[3 * p + 1] - g1, d2 = rp[3 * p + 2] - g2;
            sum += d0 * d0 + d1 * d1 + d2 * d2;
            cnt += 1.f;
            mn0 = fminf(mn0, g0); mn1 = fminf(mn1, g1); mn2 = fminf(mn2, g2);
            mx0 = fmaxf(mx0, g0); mx1 = fmaxf(mx1, g1); mx2 = fmaxf(mx2, g2);
        }
    }
    int t = threadIdx.x;
    BRED(sum, ADDOP, g_rec_sum[rb]);
    BRED(cnt, ADDOP, g_rec_cnt[rb]);
    BRED(mn0, fminf, g_rec_mn[0 * REC_BLOCKS + rb]);
    BRED(mn1, fminf, g_rec_mn[1 * REC_BLOCKS + rb]);
    BRED(mn2, fminf, g_rec_mn[2 * REC_BLOCKS + rb]);
    BRED(mx0, fmaxf, g_rec_mx[0 * REC_BLOCKS + rb]);
    BRED(mx1, fmaxf, g_rec_mx[1 * REC_BLOCKS + rb]);
    BRED(mx2, fmaxf, g_rec_mx[2 * REC_BLOCKS + rb]);
}

// ---------------------------------------------------------------------------
// ident part
// ---------------------------------------------------------------------------
__device__ void ident_part(int blk, const float* __restrict__ pred,
                           const float* __restrict__ proj,
                           const float* __restrict__ tracks, float* red) {
    int v = blk >> 6;
    int b = (blk >> 4) & 3;
    int f = blk & 15;
    int t = threadIdx.x;

    __shared__ float P[12];
    __shared__ float swh[2];
    __shared__ float sres[4];
    if (t < 12) P[t] = proj[(v * 4 + b) * 12 + t];

    const float* tr = tracks + (size_t)(((v * 4 + b) * 16 + f) * 1024) * 2;
    const float* pp = pred + (size_t)((b * 16 + f) * 1024) * 3;

    float mn0 = 1e30f, mn1 = 1e30f, mx0 = -1e30f, mx1 = -1e30f;
    for (int n = t; n < 1024; n += THREADS) {
        float a0 = tr[2 * n], a1 = tr[2 * n + 1];
        if (fabsf(a0) + fabsf(a1) > 1e-6f) {
            mn0 = fminf(mn0, a0); mn1 = fminf(mn1, a1);
            mx0 = fmaxf(mx0, a0); mx1 = fmaxf(mx1, a1);
        }
    }
    BRED(mn0, fminf, sres[0]);
    BRED(mn1, fminf, sres[1]);
    BRED(mx0, fmaxf, sres[2]);
    BRED(mx1, fmaxf, sres[3]);
    if (t == 0) {
        // no valid point: mx-mn = -2e30 -> max(224, ...) = 224, matches reference
        swh[0] = fmaxf(224.0f, sres[2] - sres[0] + 1e-6f);
        swh[1] = fmaxf(224.0f, sres[3] - sres[1] + 1e-6f);
    }
    __syncthreads();
    float wh0 = swh[0], wh1 = swh[1];

    float s = 0.f;
    for (int n = t; n < 1024; n += THREADS) {
        float px = pp[3 * n], py = pp[3 * n + 1], pz = pp[3 * n + 2];
        // Left-to-right FMA contraction, matching XLA's k-loop order.
        float h0 = __fmul_rn(P[0], px);
        h0 = __fmaf_rn(P[1], py, h0);
        h0 = __fmaf_rn(P[2], pz, h0);
        h0 = __fadd_rn(h0, P[3]);
        float h1 = __fmul_rn(P[4], px);
        h1 = __fmaf_rn(P[5], py, h1);
        h1 = __fmaf_rn(P[6], pz, h1);
        h1 = __fadd_rn(h1, P[7]);
        float h2 = __fmul_rn(P[8], px);
        h2 = __fmaf_rn(P[9], py, h2);
        h2 = __fmaf_rn(P[10], pz, h2);
        h2 = __fadd_rn(h2, P[11]);

        float d = __fadd_rn(h2, 1e-10f);
        float p20 = __fdiv_rn(h0, d);
        float p21 = __fdiv_rn(h1, d);
        float a0 = tr[2 * n], a1 = tr[2 * n + 1];
        float e0 = __fdiv_rn(__fadd_rn(p20, -a0), wh0);
        float e1 = __fdiv_rn(__fadd_rn(p21, -a1), wh1);
        s += __fmul_rn(e0, e0) + __fmul_rn(e1, e1);
    }
    BRED(s, ADDOP, g_ident[blk]);
    if (t == 0) g_ident[blk] *= (1.0f / 1024.0f);
}

// ---------------------------------------------------------------------------
// fused kernel; last-arriving block does the deterministic combine.
// ---------------------------------------------------------------------------
__global__ void __launch_bounds__(THREADS)
fused_kernel(const float* __restrict__ rp, const float* __restrict__ gp,
             const int* __restrict__ vis, const float* __restrict__ proj,
             const float* __restrict__ tracks,
             const float4* __restrict__ corr, float* __restrict__ out) {
    __shared__ float red[THREADS];
    __shared__ int sdone;
    int bid = blockIdx.x;

    if (bid < ATT_BLOCKS) {
        att_part(bid, corr, red);
    } else if (bid < REC_BASE) {
        band_part(bid - BAND_BASE, (const float*)corr, vis, red);
    } else if (bid < IDENT_BASE) {
        rec_part(bid - REC_BASE, rp, gp, vis, red);
    } else {
        ident_part(bid - IDENT_BASE, rp, proj, tracks, red);
    }

    __syncthreads();
    if (threadIdx.x == 0) {
        __threadfence();
        unsigned old = atomicAdd(&g_count, 1u);
        sdone = (old == GRID_TOTAL - 1) ? 1 : 0;
    }
    __syncthreads();
    if (!sdone) return;

    int tid = threadIdx.x;

    // attention = stream softplus sum + band correction
    float a = 0.f;
    for (int k = tid; k < ATT_BLOCKS; k += THREADS) a += __ldcg(&g_att_partial[k]);
    if (tid < BAND_BLOCKS) a += __ldcg(&g_band[tid]);
    red[tid] = a; __syncthreads();
    for (int s = THREADS / 2; s > 0; s >>= 1) {
        if (tid < s) red[tid] += red[tid + s];
        __syncthreads();
    }
    float att = red[0] * (1.0f / 67108864.0f);
    __syncthreads();

    // identity
    red[tid] = __ldcg(&g_ident[tid]); __syncthreads();
    for (int s = THREADS / 2; s > 0; s >>= 1) {
        if (tid < s) red[tid] += red[tid + s];
        __syncthreads();
    }
    float ident = red[0] * (1.0f / 256.0f);
    __syncthreads();

    // reconstruction
    red[tid] = (tid < REC_BLOCKS) ? __ldcg(&g_rec_sum[tid]) : 0.f; __syncthreads();
    for (int s = THREADS / 2; s > 0; s >>= 1) {
        if (tid < s) red[tid] += red[tid + s];
        __syncthreads();
    }
    float recSum = red[0]; __syncthreads();

    red[tid] = (tid < REC_BLOCKS) ? __ldcg(&g_rec_cnt[tid]) : 0.f; __syncthreads();
    for (int s = THREADS / 2; s > 0; s >>= 1) {
        if (tid < s) red[tid] += red[tid + s];
        __syncthreads();
    }
    float cnt = red[0]; __syncthreads();

    float mn[3], mx[3];
#pragma unroll
    for (int c = 0; c < 3; ++c) {
        red[tid] = (tid < REC_BLOCKS) ? __ldcg(&g_rec_mn[c * REC_BLOCKS + tid]) : 1e30f;
        __syncthreads();
        for (int s = THREADS / 2; s > 0; s >>= 1) {
            if (tid < s) red[tid] = fminf(red[tid], red[tid + s]);
            __syncthreads();
        }
        mn[c] = red[0]; __syncthreads();
        red[tid] = (tid < REC_BLOCKS) ? __ldcg(&g_rec_mx[c * REC_BLOCKS + tid]) : -1e30f;
        __syncthreads();
        for (int s = THREADS / 2; s > 0; s >>= 1) {
            if (tid < s) red[tid] = fmaxf(red[tid], red[tid + s]);
            __syncthreads();
        }
        mx[c] = red[0]; __syncthreads();
    }

    if (tid == 0) {
        float num = cnt * 3.0f;
        float mse = recSum / fmaxf(num, 1.0f);
        float sc = fmaxf(fmaxf(mx[0] - mn[0], mx[1] - mn[1]), mx[2] - mn[2]) + 1e-6f;
        if (!(num > 0.f)) sc = 1.0f;
        float rec = mse / (sc * sc);
        out[0] = rec + ident + 0.5f * att;
        out[1] = rec;
        out[2] = ident;
        out[3] = att;
        g_count = 0;   // reset for next graph replay
    }
}

extern "C" void kernel_launch(void* const* d_in, const int* in_sizes, int n_in,
                              void* d_out, int out_size) {
    const float*  rp     = (const float*)d_in[0];   // refined_points [4,16,1024,3]
    const float*  gp     = (const float*)d_in[1];   // gt_points
    const int*    vis    = (const int*)d_in[2];     // visibility [4,16,1024]
    const float*  proj   = (const float*)d_in[3];   // projection [4,4,3,4]
    const float*  tracks = (const float*)d_in[4];   // tracks_2d [4,4,16,1024,2]
    const float4* corr   = (const float4*)d_in[5];  // corr [4,4,4,1024,1024]

    fused_kernel<<<GRID_TOTAL, THREADS>>>(rp, gp, vis, proj, tracks, corr, (float*)d_out);
}